// round 4
// baseline (speedup 1.0000x reference)
#include <cuda_runtime.h>
#include <math.h>
#include <cstdint>

#define B_  64
#define T_  218
#define D_  512
#define R_  (B_*T_)      // 13952 = 109*128
#define H_  4
#define DK_ 128
#define QKVW (3*D_)      // 1536

// ---------------- scratch (device globals; no allocations allowed) ----------
__device__ float g_h[R_*D_];
__device__ float g_qkv[R_*QKVW];
__device__ float g_vm[R_*D_];
__device__ float g_fsmn[R_*D_];
__device__ float g_ctx[R_*D_];
__device__ float g_x1[R_*D_];
__device__ float g_mid[R_*2048];
__device__ float g_qkv_wt[QKVW*D_];           // [N,K] tf32-rounded
__device__ float g_out_wt[D_*D_];
__device__ float g_w1t[2048*D_];
__device__ float g_w2t[D_*2048];
__device__ float g_kwt[11*D_*D_];             // [tap][dout][din] tf32-rounded

// ---------------- helpers ----------------------------------------------------
__device__ __forceinline__ float rna_tf32(float x) {
    float r; asm("cvt.rna.tf32.f32 %0,%1;" : "=f"(r) : "f"(x)); return r;
}
__device__ __forceinline__ uint32_t smem_u32(const void* p) {
    uint32_t a;
    asm("{ .reg .u64 t; cvta.to.shared.u64 t, %1; cvt.u32.u64 %0, t; }" : "=r"(a) : "l"(p));
    return a;
}
__device__ __forceinline__ void cp16(uint32_t dst, const void* src, bool pred) {
    int sz = pred ? 16 : 0;
    asm volatile("cp.async.ca.shared.global [%0], [%1], 16, %2;"
                 :: "r"(dst), "l"(src), "r"(sz) : "memory");
}
#define CP_COMMIT() asm volatile("cp.async.commit_group;" ::: "memory")
#define CP_WAIT1()  asm volatile("cp.async.wait_group 1;" ::: "memory")
#define CP_WAIT0()  asm volatile("cp.async.wait_group 0;" ::: "memory")

#define MMA(d, a, b0, b1) \
    asm volatile("mma.sync.aligned.m16n8k8.row.col.f32.tf32.tf32.f32 " \
                 "{%0,%1,%2,%3},{%4,%5,%6,%7},{%8,%9},{%0,%1,%2,%3};" \
                 : "+f"((d)[0]), "+f"((d)[1]), "+f"((d)[2]), "+f"((d)[3]) \
                 : "r"((a)[0]), "r"((a)[1]), "r"((a)[2]), "r"((a)[3]), \
                   "r"(b0), "r"(b1))

#define LDW 36                       // padded row width (floats), conflict-free
#define TILEF (128*LDW)              // floats per tile buffer
#define NSTAGE 3
#define DSMEM_BYTES (NSTAGE*2*TILEF*4)   // 110592 B

// ---------------- weight transpose (+tf32 round) ----------------------------
__global__ void transpose_rna(const float* __restrict__ src, float* __restrict__ dst,
                              int Kd, int Nd) {
    __shared__ float t[32][33];
    int k0 = blockIdx.y * 32, n0 = blockIdx.x * 32;
    int x = threadIdx.x, y = threadIdx.y;   // (32,8)
#pragma unroll
    for (int i = 0; i < 32; i += 8)
        t[y + i][x] = src[(size_t)(k0 + y + i) * Nd + n0 + x];
    __syncthreads();
#pragma unroll
    for (int i = 0; i < 32; i += 8)
        dst[(size_t)(n0 + y + i) * Kd + k0 + x] = rna_tf32(t[x][y + i]);
}

__global__ void kw_transpose(const float* __restrict__ fw) {
    int idx = blockIdx.x * 256 + threadIdx.x;
    if (idx >= 11 * D_ * D_) return;
    int tap = idx / (D_ * D_);
    int rem = idx % (D_ * D_);
    int dout = rem / D_;
    int din = rem % D_;
    g_kwt[idx] = rna_tf32(fw[((size_t)dout * D_ + din) * 11 + tap]);
}

// ---------------- layer norm (tf32-rounded output) --------------------------
__global__ void ln_kernel(const float* __restrict__ x, const float* __restrict__ w,
                          const float* __restrict__ b, float* __restrict__ out) {
    int row = blockIdx.x;
    const float* xr = x + (size_t)row * D_;
    float* orow = out + (size_t)row * D_;
    float v[4];
    float s = 0.f, sq = 0.f;
#pragma unroll
    for (int i = 0; i < 4; i++) {
        v[i] = xr[threadIdx.x + i * 128];
        s += v[i]; sq += v[i] * v[i];
    }
    __shared__ float sm[8];
#pragma unroll
    for (int o = 16; o; o >>= 1) {
        s  += __shfl_xor_sync(~0u, s, o);
        sq += __shfl_xor_sync(~0u, sq, o);
    }
    int lane = threadIdx.x & 31, wid = threadIdx.x >> 5;
    if (lane == 0) { sm[wid] = s; sm[4 + wid] = sq; }
    __syncthreads();
    if (threadIdx.x == 0) {
        float S = sm[0] + sm[1] + sm[2] + sm[3];
        float SQ = sm[4] + sm[5] + sm[6] + sm[7];
        float mean = S * (1.f / D_);
        float var = SQ * (1.f / D_) - mean * mean;
        sm[0] = mean;
        sm[1] = rsqrtf(var + 1e-5f);
    }
    __syncthreads();
    float mean = sm[0], inv = sm[1];
#pragma unroll
    for (int i = 0; i < 4; i++) {
        int c = threadIdx.x + i * 128;
        orow[c] = rna_tf32((v[i] - mean) * inv * w[c] + b[c]);
    }
}

// ---------------- tf32 mma.sync GEMM, 3-stage pipeline ----------------------
// C[M,N] = A[M,K] @ Bt[N,K]^T + bias
// epi: 0=bias; 1=bias+relu+round; 2=bias+add1+add2; 3=bias+add1;
//      5=bias, and for cols>=1024 also write vm=rna(v*mask) (add1=masks, add2=vm)
__global__ void __launch_bounds__(256)
tgemm(const float* __restrict__ A, const float* __restrict__ Bt,
      const float* __restrict__ bias, float* __restrict__ C,
      int N, int K, int epi,
      const float* __restrict__ add1, float* __restrict__ add2) {
    extern __shared__ float smf[];
    int tid = threadIdx.x;
    int lane = tid & 31, wid = tid >> 5;
    int wm = (wid & 3) * 32;
    int wn = (wid >> 2) * 64;
    int g = lane >> 2, c = lane & 3;
    int rowBase = blockIdx.y * 128, colBase = blockIdx.x * 128;

    int srow[4], sseg[4];
#pragma unroll
    for (int u = 0; u < 4; u++) {
        int f = tid + 256 * u;
        srow[u] = f >> 3;
        sseg[u] = f & 7;
    }

    float acc[2][8][4];
#pragma unroll
    for (int i = 0; i < 2; i++)
#pragma unroll
        for (int j = 0; j < 8; j++)
#pragma unroll
            for (int q = 0; q < 4; q++) acc[i][j][q] = 0.f;

    int nk = K >> 5;
    const float* Arow = A + (size_t)rowBase * K;
    const float* Brow = Bt + (size_t)colBase * K;

    // prologue: stage 0 and 1
#pragma unroll
    for (int s = 0; s < 2; s++) {
        float* Ab = smf + s * 2 * TILEF;
        float* Bb = Ab + TILEF;
#pragma unroll
        for (int u = 0; u < 4; u++) {
            cp16(smem_u32(Ab + srow[u] * LDW + sseg[u] * 4),
                 Arow + (size_t)srow[u] * K + s * 32 + sseg[u] * 4, true);
            cp16(smem_u32(Bb + srow[u] * LDW + sseg[u] * 4),
                 Brow + (size_t)srow[u] * K + s * 32 + sseg[u] * 4, true);
        }
        CP_COMMIT();
    }

    for (int kt = 0; kt < nk; kt++) {
        if (kt + 1 < nk) CP_WAIT1(); else CP_WAIT0();
        __syncthreads();
        if (kt + 2 < nk) {
            int ns = (kt + 2) % NSTAGE;
            float* Ab = smf + ns * 2 * TILEF;
            float* Bb = Ab + TILEF;
#pragma unroll
            for (int u = 0; u < 4; u++) {
                cp16(smem_u32(Ab + srow[u] * LDW + sseg[u] * 4),
                     Arow + (size_t)srow[u] * K + (kt + 2) * 32 + sseg[u] * 4, true);
                cp16(smem_u32(Bb + srow[u] * LDW + sseg[u] * 4),
                     Brow + (size_t)srow[u] * K + (kt + 2) * 32 + sseg[u] * 4, true);
            }
            CP_COMMIT();
        }
        const float* As = smf + (kt % NSTAGE) * 2 * TILEF;
        const float* Bs = As + TILEF;
#pragma unroll
        for (int ks = 0; ks < 4; ks++) {
            int kk = ks * 8;
            uint32_t a[2][4];
#pragma unroll
            for (int mt = 0; mt < 2; mt++) {
                const float* ap = As + (wm + mt * 16) * LDW + kk;
                a[mt][0] = __float_as_uint(ap[g * LDW + c]);
                a[mt][1] = __float_as_uint(ap[(g + 8) * LDW + c]);
                a[mt][2] = __float_as_uint(ap[g * LDW + c + 4]);
                a[mt][3] = __float_as_uint(ap[(g + 8) * LDW + c + 4]);
            }
#pragma unroll
            for (int nt = 0; nt < 8; nt++) {
                const float* bp = Bs + (wn + nt * 8 + g) * LDW + kk;
                uint32_t b0 = __float_as_uint(bp[c]);
                uint32_t b1 = __float_as_uint(bp[c + 4]);
                MMA(acc[0][nt], a[0], b0, b1);
                MMA(acc[1][nt], a[1], b0, b1);
            }
        }
        __syncthreads();  // protect smem reuse: next iteration stages into (kt+2)%3 == (kt-1)%3
    }

    // epilogue
#pragma unroll
    for (int mt = 0; mt < 2; mt++) {
#pragma unroll
        for (int nt = 0; nt < 8; nt++) {
            int cb = colBase + wn + nt * 8 + 2 * c;
            float bs0 = bias[cb], bs1 = bias[cb + 1];
#pragma unroll
            for (int half = 0; half < 2; half++) {
                int r = rowBase + wm + mt * 16 + g + half * 8;
                float v0 = acc[mt][nt][half * 2 + 0] + bs0;
                float v1 = acc[mt][nt][half * 2 + 1] + bs1;
                if (epi == 1) {
                    v0 = rna_tf32(fmaxf(v0, 0.f));
                    v1 = rna_tf32(fmaxf(v1, 0.f));
                } else if (epi == 2) {
                    size_t id = (size_t)r * 512 + cb;
                    v0 += add1[id] + ((const float*)add2)[id];
                    v1 += add1[id + 1] + ((const float*)add2)[id + 1];
                } else if (epi == 3) {
                    size_t id = (size_t)r * 512 + cb;
                    v0 += add1[id];
                    v1 += add1[id + 1];
                }
                *(float2*)(C + (size_t)r * N + cb) = make_float2(v0, v1);
                if (epi == 5 && cb >= 1024) {
                    float m = add1[r];
                    add2[(size_t)r * 512 + cb - 1024]     = rna_tf32(v0 * m);
                    add2[(size_t)r * 512 + cb - 1024 + 1] = rna_tf32(v1 * m);
                }
            }
        }
    }
}

// ---------------- FSMN conv via mma.sync: 11 shifted GEMMs, 3-stage ---------
__global__ void __launch_bounds__(256)
tconv(const float* __restrict__ vm, const float* __restrict__ qkv,
      const float* __restrict__ masks, float* __restrict__ out) {
    extern __shared__ float smf[];
    int tid = threadIdx.x;
    int lane = tid & 31, wid = tid >> 5;
    int wm = (wid & 3) * 32;
    int wn = (wid >> 2) * 64;
    int g = lane >> 2, c = lane & 3;
    int rowBase = blockIdx.y * 128, colBase = blockIdx.x * 128;

    int srow[4], sseg[4], sb[4], st[4];
#pragma unroll
    for (int u = 0; u < 4; u++) {
        int f = tid + 256 * u;
        srow[u] = f >> 3;
        sseg[u] = f & 7;
        int grow = rowBase + srow[u];
        sb[u] = grow / T_;
        st[u] = grow - sb[u] * T_;
    }

    float acc[2][8][4];
#pragma unroll
    for (int i = 0; i < 2; i++)
#pragma unroll
        for (int j = 0; j < 8; j++)
#pragma unroll
            for (int q = 0; q < 4; q++) acc[i][j][q] = 0.f;

    const int NT = 11 * 16;

    // stage helper expressed inline: iteration ti -> (tap, kt)
#pragma unroll
    for (int s = 0; s < 2; s++) {
        int tap = s >> 4, kt = s & 15;   // s in {0,1} => tap=0
        float* Ab = smf + s * 2 * TILEF;
        float* Bb = Ab + TILEF;
        const float* Bg = g_kwt + (size_t)tap * D_ * D_ + (size_t)colBase * D_ + kt * 32;
#pragma unroll
        for (int u = 0; u < 4; u++) {
            int src = st[u] + tap - 5;
            bool ok = (unsigned)src < (unsigned)T_;
            cp16(smem_u32(Ab + srow[u] * LDW + sseg[u] * 4),
                 vm + ((size_t)(sb[u] * T_ + (ok ? src : 0)) * D_ + kt * 32 + sseg[u] * 4), ok);
            cp16(smem_u32(Bb + srow[u] * LDW + sseg[u] * 4),
                 Bg + (size_t)srow[u] * D_ + sseg[u] * 4, true);
        }
        CP_COMMIT();
    }

    for (int ti = 0; ti < NT; ti++) {
        if (ti + 1 < NT) CP_WAIT1(); else CP_WAIT0();
        __syncthreads();
        if (ti + 2 < NT) {
            int t2 = ti + 2;
            int tap = t2 >> 4, kt = t2 & 15;
            int ns = t2 % NSTAGE;
            float* Ab = smf + ns * 2 * TILEF;
            float* Bb = Ab + TILEF;
            const float* Bg = g_kwt + (size_t)tap * D_ * D_ + (size_t)colBase * D_ + kt * 32;
#pragma unroll
            for (int u = 0; u < 4; u++) {
                int src = st[u] + tap - 5;
                bool ok = (unsigned)src < (unsigned)T_;
                cp16(smem_u32(Ab + srow[u] * LDW + sseg[u] * 4),
                     vm + ((size_t)(sb[u] * T_ + (ok ? src : 0)) * D_ + kt * 32 + sseg[u] * 4), ok);
                cp16(smem_u32(Bb + srow[u] * LDW + sseg[u] * 4),
                     Bg + (size_t)srow[u] * D_ + sseg[u] * 4, true);
            }
            CP_COMMIT();
        }
        const float* As = smf + (ti % NSTAGE) * 2 * TILEF;
        const float* Bs = As + TILEF;
#pragma unroll
        for (int ks = 0; ks < 4; ks++) {
            int kk = ks * 8;
            uint32_t a[2][4];
#pragma unroll
            for (int mt = 0; mt < 2; mt++) {
                const float* ap = As + (wm + mt * 16) * LDW + kk;
                a[mt][0] = __float_as_uint(ap[g * LDW + c]);
                a[mt][1] = __float_as_uint(ap[(g + 8) * LDW + c]);
                a[mt][2] = __float_as_uint(ap[g * LDW + c + 4]);
                a[mt][3] = __float_as_uint(ap[(g + 8) * LDW + c + 4]);
            }
#pragma unroll
            for (int nt = 0; nt < 8; nt++) {
                const float* bp = Bs + (wn + nt * 8 + g) * LDW + kk;
                uint32_t b0 = __float_as_uint(bp[c]);
                uint32_t b1 = __float_as_uint(bp[c + 4]);
                MMA(acc[0][nt], a[0], b0, b1);
                MMA(acc[1][nt], a[1], b0, b1);
            }
        }
        __syncthreads();
    }

    // epilogue: out = (acc + v*m) * m
#pragma unroll
    for (int mt = 0; mt < 2; mt++) {
#pragma unroll
        for (int nt = 0; nt < 8; nt++) {
            int cb = colBase + wn + nt * 8 + 2 * c;
#pragma unroll
            for (int half = 0; half < 2; half++) {
                int r = rowBase + wm + mt * 16 + g + half * 8;
                float m = masks[r];
                float v0 = qkv[(size_t)r * QKVW + 1024 + cb];
                float v1 = qkv[(size_t)r * QKVW + 1024 + cb + 1];
                float o0 = (acc[mt][nt][half * 2 + 0] + v0 * m) * m;
                float o1 = (acc[mt][nt][half * 2 + 1] + v1 * m) * m;
                *(float2*)(out + (size_t)r * D_ + cb) = make_float2(o0, o1);
            }
        }
    }
}

// ---------------- fused attention: scores + softmax + ctx -------------------
// grid: (qtiles=7, bh=256), block 256. scores kept in smem.
#define QT 32
#define SCPAD 224
#define ATT_SMEM ((QT*132 + QT*132 + QT*SCPAD)*4)
__global__ void __launch_bounds__(256)
att_kernel(const float* __restrict__ qkv, const float* __restrict__ masks,
           float* __restrict__ ctx) {
    extern __shared__ float smf[];
    float* Qs = smf;                 // [QT][132]
    float* Ks = smf + QT * 132;      // [QT][132]
    float* Sc = smf + 2 * QT * 132;  // [QT][SCPAD]
    int tid = threadIdx.x;
    int bh = blockIdx.y;
    int b = bh >> 2, h = bh & 3;
    int qbase = blockIdx.x * QT;
    int nq = T_ - qbase; if (nq > QT) nq = QT;
    const int qoff = h * DK_;
    const int koff = D_ + h * DK_;
    const int voff = 1024 + h * DK_;

    // stage Q tile: 32 rows x 128 cols
    for (int f = tid; f < QT * 32; f += 256) {
        int row = f >> 5, seg = f & 31;
        float4 v = make_float4(0.f, 0.f, 0.f, 0.f);
        if (row < nq)
            v = *(const float4*)(qkv + (size_t)(b * T_ + qbase + row) * QKVW + qoff + seg * 4);
        *(float4*)(Qs + row * 132 + seg * 4) = v;
    }
    __syncthreads();

    int tx = tid & 15, ty = tid >> 4;
    const float scale = 0.08838834764831845f;
    for (int kbase = 0; kbase < T_; kbase += 32) {
        int nk2 = T_ - kbase; if (nk2 > 32) nk2 = 32;
        // stage K tile
        for (int f = tid; f < 32 * 32; f += 256) {
            int row = f >> 5, seg = f & 31;
            float4 v = make_float4(0.f, 0.f, 0.f, 0.f);
            if (row < nk2)
                v = *(const float4*)(qkv + (size_t)(b * T_ + kbase + row) * QKVW + koff + seg * 4);
            *(float4*)(Ks + row * 132 + seg * 4) = v;
        }
        __syncthreads();
        float acc[2][2] = {};
        const float* q0p = Qs + (ty * 2 + 0) * 132;
        const float* q1p = Qs + (ty * 2 + 1) * 132;
        const float* k0p = Ks + (tx * 2 + 0) * 132;
        const float* k1p = Ks + (tx * 2 + 1) * 132;
#pragma unroll 4
        for (int d = 0; d < DK_; d++) {
            float q0 = q0p[d], q1 = q1p[d];
            float k0 = k0p[d], k1 = k1p[d];
            acc[0][0] += q0 * k0; acc[0][1] += q0 * k1;
            acc[1][0] += q1 * k0; acc[1][1] += q1 * k1;
        }
#pragma unroll
        for (int i = 0; i < 2; i++) {
#pragma unroll
            for (int j = 0; j < 2; j++) {
                int kc = kbase + tx * 2 + j;
                if (kc < T_) {
                    float s = acc[i][j] * scale;
                    if (masks[b * T_ + kc] <= 0.f) s = -3.0e38f;
                    Sc[(ty * 2 + i) * SCPAD + kc] = s;
                }
            }
        }
        __syncthreads();
    }

    // softmax: warp w handles rows w*4..w*4+3
    int lane = tid & 31, wrp = tid >> 5;
#pragma unroll
    for (int i = 0; i < 4; i++) {
        int row = wrp * 4 + i;
        float* p = Sc + row * SCPAD;
        float mx = -3.4e38f;
        for (int k = lane; k < T_; k += 32) mx = fmaxf(mx, p[k]);
#pragma unroll
        for (int o = 16; o; o >>= 1) mx = fmaxf(mx, __shfl_xor_sync(~0u, mx, o));
        float sum = 0.f;
        for (int k = lane; k < T_; k += 32) {
            float e = expf(p[k] - mx);
            p[k] = e;
            sum += e;
        }
#pragma unroll
        for (int o = 16; o; o >>= 1) sum += __shfl_xor_sync(~0u, sum, o);
        float inv = 1.f / sum;
        for (int k = lane; k < T_; k += 32) p[k] *= inv;
    }
    __syncthreads();

    // ctx: thread handles col = tid&127, rows (tid>>7)*16 .. +15
    int c = tid & 127;
    int rg = (tid >> 7) * 16;
    float acc[16];
#pragma unroll
    for (int i = 0; i < 16; i++) acc[i] = 0.f;
    for (int k = 0; k < T_; k++) {
        float vk = qkv[(size_t)(b * T_ + k) * QKVW + voff + c];
#pragma unroll
        for (int i = 0; i < 16; i++)
            acc[i] += Sc[(rg + i) * SCPAD + k] * vk;
    }
#pragma unroll
    for (int i = 0; i < 16; i++) {
        int r = qbase + rg + i;
        if (r < T_)
            ctx[(size_t)(b * T_ + r) * D_ + h * DK_ + c] = rna_tf32(acc[i]);
    }
}

// ---------------- launch ------------------------------------------------------
extern "C" void kernel_launch(void* const* d_in, const int* in_sizes, int n_in,
                              void* d_out, int out_size) {
    const float* x     = (const float*)d_in[0];
    const float* masks = (const float*)d_in[1];
    const float* ln0_w = (const float*)d_in[2];
    const float* ln0_b = (const float*)d_in[3];
    const float* ln1_w = (const float*)d_in[4];
    const float* ln1_b = (const float*)d_in[5];
    const float* qkv_w = (const float*)d_in[6];
    const float* qkv_b = (const float*)d_in[7];
    const float* out_w = (const float*)d_in[8];
    const float* out_b = (const float*)d_in[9];
    const float* fsmn_w= (const float*)d_in[10];
    const float* w1    = (const float*)d_in[11];
    const float* b1    = (const float*)d_in[12];
    const float* w2    = (const float*)d_in[13];
    const float* b2    = (const float*)d_in[14];
    float* out = (float*)d_out;

    float *h, *qkv, *vm, *fsmn, *ctx, *x1, *mid;
    float *qkv_wt, *out_wt, *w1t, *w2t;
    cudaGetSymbolAddress((void**)&h,      g_h);
    cudaGetSymbolAddress((void**)&qkv,    g_qkv);
    cudaGetSymbolAddress((void**)&vm,     g_vm);
    cudaGetSymbolAddress((void**)&fsmn,   g_fsmn);
    cudaGetSymbolAddress((void**)&ctx,    g_ctx);
    cudaGetSymbolAddress((void**)&x1,     g_x1);
    cudaGetSymbolAddress((void**)&mid,    g_mid);
    cudaGetSymbolAddress((void**)&qkv_wt, g_qkv_wt);
    cudaGetSymbolAddress((void**)&out_wt, g_out_wt);
    cudaGetSymbolAddress((void**)&w1t,    g_w1t);
    cudaGetSymbolAddress((void**)&w2t,    g_w2t);

    cudaFuncSetAttribute(tgemm, cudaFuncAttributeMaxDynamicSharedMemorySize, DSMEM_BYTES);
    cudaFuncSetAttribute(tconv, cudaFuncAttributeMaxDynamicSharedMemorySize, DSMEM_BYTES);
    cudaFuncSetAttribute(att_kernel, cudaFuncAttributeMaxDynamicSharedMemorySize, ATT_SMEM);

    // weight prep (tf32-rounded, [N,K] layouts)
    transpose_rna<<<dim3(QKVW / 32, D_ / 32), dim3(32, 8)>>>(qkv_w, qkv_wt, D_, QKVW);
    transpose_rna<<<dim3(D_ / 32, D_ / 32), dim3(32, 8)>>>(out_w, out_wt, D_, D_);
    transpose_rna<<<dim3(2048 / 32, D_ / 32), dim3(32, 8)>>>(w1, w1t, D_, 2048);
    transpose_rna<<<dim3(D_ / 32, 2048 / 32), dim3(32, 8)>>>(w2, w2t, 2048, D_);
    kw_transpose<<<(11 * D_ * D_ + 255) / 256, 256>>>(fsmn_w);

    // LN0 (rounded)
    ln_kernel<<<R_, 128>>>(x, ln0_w, ln0_b, h);

    // QKV (epi 5: also writes vm for v columns)
    tgemm<<<dim3(QKVW / 128, R_ / 128), 256, DSMEM_BYTES>>>(h, qkv_wt, qkv_b, qkv,
                                                            QKVW, D_, 5, masks, vm);

    // FSMN conv
    tconv<<<dim3(D_ / 128, R_ / 128), 256, DSMEM_BYTES>>>(vm, qkv, masks, fsmn);

    // fused attention
    att_kernel<<<dim3((T_ + QT - 1) / QT, B_ * H_), 256, ATT_SMEM>>>(qkv, masks, ctx);

    // out proj + fsmn + residual
    tgemm<<<dim3(D_ / 128, R_ / 128), 256, DSMEM_BYTES>>>(ctx, out_wt, out_b, x1,
                                                          D_, D_, 2, fsmn, (float*)x);
    // LN1
    ln_kernel<<<R_, 128>>>(x1, ln1_w, ln1_b, h);

    // FFN
    tgemm<<<dim3(2048 / 128, R_ / 128), 256, DSMEM_BYTES>>>(h, w1t, b1, mid,
                                                            2048, D_, 1, nullptr, nullptr);
    tgemm<<<dim3(D_ / 128, R_ / 128), 256, DSMEM_BYTES>>>(mid, w2t, b2, out,
                                                          D_, 2048, 3, x1, nullptr);
    (void)in_sizes; (void)n_in; (void)out_size;
}

// round 5
// speedup vs baseline: 1.0012x; 1.0012x over previous
#include <cuda_runtime.h>
#include <math.h>
#include <cstdint>

#define B_  64
#define T_  218
#define D_  512
#define R_  (B_*T_)      // 13952 = 109*128
#define H_  4
#define DK_ 128
#define QKVW (3*D_)      // 1536

// ---------------- scratch (device globals; no allocations allowed) ----------
__device__ float g_h[R_*D_];
__device__ float g_qkv[R_*QKVW];
__device__ float g_vm[R_*D_];
__device__ float g_fsmn[R_*D_];
__device__ float g_ctx[R_*D_];
__device__ float g_x1[R_*D_];
__device__ float g_mid[R_*2048];
__device__ float g_qkv_wt[QKVW*D_];           // [N,K] tf32-rounded
__device__ float g_out_wt[D_*D_];
__device__ float g_w1t[2048*D_];
__device__ float g_w2t[D_*2048];
__device__ float g_kwt[11*D_*D_];             // [tap][dout][din] tf32-rounded

// ---------------- helpers ----------------------------------------------------
__device__ __forceinline__ float rna_tf32(float x) {
    float r; asm("cvt.rna.tf32.f32 %0,%1;" : "=f"(r) : "f"(x)); return r;
}
__device__ __forceinline__ uint32_t smem_u32(const void* p) {
    uint32_t a;
    asm("{ .reg .u64 t; cvta.to.shared.u64 t, %1; cvt.u32.u64 %0, t; }" : "=r"(a) : "l"(p));
    return a;
}
__device__ __forceinline__ void cp16(uint32_t dst, const void* src, bool pred) {
    int sz = pred ? 16 : 0;
    asm volatile("cp.async.ca.shared.global [%0], [%1], 16, %2;"
                 :: "r"(dst), "l"(src), "r"(sz) : "memory");
}
#define CP_COMMIT() asm volatile("cp.async.commit_group;" ::: "memory")
#define CP_WAIT1()  asm volatile("cp.async.wait_group 1;" ::: "memory")
#define CP_WAIT0()  asm volatile("cp.async.wait_group 0;" ::: "memory")

#define MMA(d, a, b0, b1) \
    asm volatile("mma.sync.aligned.m16n8k8.row.col.f32.tf32.tf32.f32 " \
                 "{%0,%1,%2,%3},{%4,%5,%6,%7},{%8,%9},{%0,%1,%2,%3};" \
                 : "+f"((d)[0]), "+f"((d)[1]), "+f"((d)[2]), "+f"((d)[3]) \
                 : "r"((a)[0]), "r"((a)[1]), "r"((a)[2]), "r"((a)[3]), \
                   "r"(b0), "r"(b1))

#define LDW 36                       // padded row width (floats), conflict-free
#define TILEF (128*LDW)              // floats per tile buffer
#define NSTAGE 3
#define DSMEM_BYTES (NSTAGE*2*TILEF*4)   // 110592 B

// ---------------- weight transpose (+tf32 round) ----------------------------
__global__ void transpose_rna(const float* __restrict__ src, float* __restrict__ dst,
                              int Kd, int Nd) {
    __shared__ float t[32][33];
    int k0 = blockIdx.y * 32, n0 = blockIdx.x * 32;
    int x = threadIdx.x, y = threadIdx.y;   // (32,8)
#pragma unroll
    for (int i = 0; i < 32; i += 8)
        t[y + i][x] = src[(size_t)(k0 + y + i) * Nd + n0 + x];
    __syncthreads();
#pragma unroll
    for (int i = 0; i < 32; i += 8)
        dst[(size_t)(n0 + y + i) * Kd + k0 + x] = rna_tf32(t[x][y + i]);
}

__global__ void kw_transpose(const float* __restrict__ fw) {
    int idx = blockIdx.x * 256 + threadIdx.x;
    if (idx >= 11 * D_ * D_) return;
    int tap = idx / (D_ * D_);
    int rem = idx % (D_ * D_);
    int dout = rem / D_;
    int din = rem % D_;
    g_kwt[idx] = rna_tf32(fw[((size_t)dout * D_ + din) * 11 + tap]);
}

// ---------------- layer norm (tf32-rounded output) --------------------------
__global__ void ln_kernel(const float* __restrict__ x, const float* __restrict__ w,
                          const float* __restrict__ b, float* __restrict__ out) {
    int row = blockIdx.x;
    const float* xr = x + (size_t)row * D_;
    float* orow = out + (size_t)row * D_;
    float v[4];
    float s = 0.f, sq = 0.f;
#pragma unroll
    for (int i = 0; i < 4; i++) {
        v[i] = xr[threadIdx.x + i * 128];
        s += v[i]; sq += v[i] * v[i];
    }
    __shared__ float sm[8];
#pragma unroll
    for (int o = 16; o; o >>= 1) {
        s  += __shfl_xor_sync(~0u, s, o);
        sq += __shfl_xor_sync(~0u, sq, o);
    }
    int lane = threadIdx.x & 31, wid = threadIdx.x >> 5;
    if (lane == 0) { sm[wid] = s; sm[4 + wid] = sq; }
    __syncthreads();
    if (threadIdx.x == 0) {
        float S = sm[0] + sm[1] + sm[2] + sm[3];
        float SQ = sm[4] + sm[5] + sm[6] + sm[7];
        float mean = S * (1.f / D_);
        float var = SQ * (1.f / D_) - mean * mean;
        sm[0] = mean;
        sm[1] = rsqrtf(var + 1e-5f);
    }
    __syncthreads();
    float mean = sm[0], inv = sm[1];
#pragma unroll
    for (int i = 0; i < 4; i++) {
        int c = threadIdx.x + i * 128;
        orow[c] = rna_tf32((v[i] - mean) * inv * w[c] + b[c]);
    }
}

// ---------------- tf32 mma.sync GEMM, 3-stage, single barrier per tile ------
// C[M,N] = A[M,K] @ Bt[N,K]^T + bias
// epi: 0=bias; 1=bias+relu+round; 2=bias+add1+add2; 3=bias+add1;
//      5=bias, and for cols>=1024 also write vm=rna(v*mask) (add1=masks, add2=vm)
__global__ void __launch_bounds__(256)
tgemm(const float* __restrict__ A, const float* __restrict__ Bt,
      const float* __restrict__ bias, float* __restrict__ C,
      int N, int K, int epi,
      const float* __restrict__ add1, float* __restrict__ add2) {
    extern __shared__ float smf[];
    int tid = threadIdx.x;
    int lane = tid & 31, wid = tid >> 5;
    int wm = (wid & 3) * 32;
    int wn = (wid >> 2) * 64;
    int g = lane >> 2, c = lane & 3;
    int rowBase = blockIdx.y * 128, colBase = blockIdx.x * 128;

    int srow[4], sseg[4];
#pragma unroll
    for (int u = 0; u < 4; u++) {
        int f = tid + 256 * u;
        srow[u] = f >> 3;
        sseg[u] = f & 7;
    }

    float acc[2][8][4];
#pragma unroll
    for (int i = 0; i < 2; i++)
#pragma unroll
        for (int j = 0; j < 8; j++)
#pragma unroll
            for (int q = 0; q < 4; q++) acc[i][j][q] = 0.f;

    int nk = K >> 5;
    const float* Arow = A + (size_t)rowBase * K;
    const float* Brow = Bt + (size_t)colBase * K;

    // prologue: stage 0 and 1
#pragma unroll
    for (int s = 0; s < 2; s++) {
        float* Ab = smf + s * 2 * TILEF;
        float* Bb = Ab + TILEF;
#pragma unroll
        for (int u = 0; u < 4; u++) {
            cp16(smem_u32(Ab + srow[u] * LDW + sseg[u] * 4),
                 Arow + (size_t)srow[u] * K + s * 32 + sseg[u] * 4, true);
            cp16(smem_u32(Bb + srow[u] * LDW + sseg[u] * 4),
                 Brow + (size_t)srow[u] * K + s * 32 + sseg[u] * 4, true);
        }
        CP_COMMIT();
    }

    for (int kt = 0; kt < nk; kt++) {
        if (kt + 1 < nk) CP_WAIT1(); else CP_WAIT0();
        __syncthreads();   // all threads finished compute(kt-1); stage kt ready
        if (kt + 2 < nk) {
            int ns = (kt + 2) % NSTAGE;   // == (kt-1)%NSTAGE: buffer just freed
            float* Ab = smf + ns * 2 * TILEF;
            float* Bb = Ab + TILEF;
#pragma unroll
            for (int u = 0; u < 4; u++) {
                cp16(smem_u32(Ab + srow[u] * LDW + sseg[u] * 4),
                     Arow + (size_t)srow[u] * K + (kt + 2) * 32 + sseg[u] * 4, true);
                cp16(smem_u32(Bb + srow[u] * LDW + sseg[u] * 4),
                     Brow + (size_t)srow[u] * K + (kt + 2) * 32 + sseg[u] * 4, true);
            }
            CP_COMMIT();
        }
        const float* As = smf + (kt % NSTAGE) * 2 * TILEF;
        const float* Bs = As + TILEF;
#pragma unroll
        for (int ks = 0; ks < 4; ks++) {
            int kk = ks * 8;
            uint32_t a[2][4];
#pragma unroll
            for (int mt = 0; mt < 2; mt++) {
                const float* ap = As + (wm + mt * 16) * LDW + kk;
                a[mt][0] = __float_as_uint(ap[g * LDW + c]);
                a[mt][1] = __float_as_uint(ap[(g + 8) * LDW + c]);
                a[mt][2] = __float_as_uint(ap[g * LDW + c + 4]);
                a[mt][3] = __float_as_uint(ap[(g + 8) * LDW + c + 4]);
            }
#pragma unroll
            for (int nt = 0; nt < 8; nt++) {
                const float* bp = Bs + (wn + nt * 8 + g) * LDW + kk;
                uint32_t b0 = __float_as_uint(bp[c]);
                uint32_t b1 = __float_as_uint(bp[c + 4]);
                MMA(acc[0][nt], a[0], b0, b1);
                MMA(acc[1][nt], a[1], b0, b1);
            }
        }
        // no trailing barrier: next iteration's barrier protects buffer reuse
    }

    // epilogue
#pragma unroll
    for (int mt = 0; mt < 2; mt++) {
#pragma unroll
        for (int nt = 0; nt < 8; nt++) {
            int cb = colBase + wn + nt * 8 + 2 * c;
            float bs0 = bias[cb], bs1 = bias[cb + 1];
#pragma unroll
            for (int half = 0; half < 2; half++) {
                int r = rowBase + wm + mt * 16 + g + half * 8;
                float v0 = acc[mt][nt][half * 2 + 0] + bs0;
                float v1 = acc[mt][nt][half * 2 + 1] + bs1;
                if (epi == 1) {
                    v0 = rna_tf32(fmaxf(v0, 0.f));
                    v1 = rna_tf32(fmaxf(v1, 0.f));
                } else if (epi == 2) {
                    size_t id = (size_t)r * 512 + cb;
                    v0 += add1[id] + ((const float*)add2)[id];
                    v1 += add1[id + 1] + ((const float*)add2)[id + 1];
                } else if (epi == 3) {
                    size_t id = (size_t)r * 512 + cb;
                    v0 += add1[id];
                    v1 += add1[id + 1];
                }
                *(float2*)(C + (size_t)r * N + cb) = make_float2(v0, v1);
                if (epi == 5 && cb >= 1024) {
                    float m = add1[r];
                    add2[(size_t)r * 512 + cb - 1024]     = rna_tf32(v0 * m);
                    add2[(size_t)r * 512 + cb - 1024 + 1] = rna_tf32(v1 * m);
                }
            }
        }
    }
}

// ---------------- FSMN conv via mma.sync: 11 shifted GEMMs, 3-stage ---------
__global__ void __launch_bounds__(256)
tconv(const float* __restrict__ vm, const float* __restrict__ qkv,
      const float* __restrict__ masks, float* __restrict__ out) {
    extern __shared__ float smf[];
    int tid = threadIdx.x;
    int lane = tid & 31, wid = tid >> 5;
    int wm = (wid & 3) * 32;
    int wn = (wid >> 2) * 64;
    int g = lane >> 2, c = lane & 3;
    int rowBase = blockIdx.y * 128, colBase = blockIdx.x * 128;

    int srow[4], sseg[4], sb[4], st[4];
#pragma unroll
    for (int u = 0; u < 4; u++) {
        int f = tid + 256 * u;
        srow[u] = f >> 3;
        sseg[u] = f & 7;
        int grow = rowBase + srow[u];
        sb[u] = grow / T_;
        st[u] = grow - sb[u] * T_;
    }

    float acc[2][8][4];
#pragma unroll
    for (int i = 0; i < 2; i++)
#pragma unroll
        for (int j = 0; j < 8; j++)
#pragma unroll
            for (int q = 0; q < 4; q++) acc[i][j][q] = 0.f;

    const int NT = 11 * 16;

    // prologue: stage iterations 0,1 (tap 0, kt 0/1)
#pragma unroll
    for (int s = 0; s < 2; s++) {
        int tap = s >> 4, kt = s & 15;
        float* Ab = smf + s * 2 * TILEF;
        float* Bb = Ab + TILEF;
        const float* Bg = g_kwt + (size_t)tap * D_ * D_ + (size_t)colBase * D_ + kt * 32;
#pragma unroll
        for (int u = 0; u < 4; u++) {
            int src = st[u] + tap - 5;
            bool ok = (unsigned)src < (unsigned)T_;
            cp16(smem_u32(Ab + srow[u] * LDW + sseg[u] * 4),
                 vm + ((size_t)(sb[u] * T_ + (ok ? src : 0)) * D_ + kt * 32 + sseg[u] * 4), ok);
            cp16(smem_u32(Bb + srow[u] * LDW + sseg[u] * 4),
                 Bg + (size_t)srow[u] * D_ + sseg[u] * 4, true);
        }
        CP_COMMIT();
    }

    for (int ti = 0; ti < NT; ti++) {
        if (ti + 1 < NT) CP_WAIT1(); else CP_WAIT0();
        __syncthreads();
        if (ti + 2 < NT) {
            int t2 = ti + 2;
            int tap = t2 >> 4, kt = t2 & 15;
            int ns = t2 % NSTAGE;
            float* Ab = smf + ns * 2 * TILEF;
            float* Bb = Ab + TILEF;
            const float* Bg = g_kwt + (size_t)tap * D_ * D_ + (size_t)colBase * D_ + kt * 32;
#pragma unroll
            for (int u = 0; u < 4; u++) {
                int src = st[u] + tap - 5;
                bool ok = (unsigned)src < (unsigned)T_;
                cp16(smem_u32(Ab + srow[u] * LDW + sseg[u] * 4),
                     vm + ((size_t)(sb[u] * T_ + (ok ? src : 0)) * D_ + kt * 32 + sseg[u] * 4), ok);
                cp16(smem_u32(Bb + srow[u] * LDW + sseg[u] * 4),
                     Bg + (size_t)srow[u] * D_ + sseg[u] * 4, true);
            }
            CP_COMMIT();
        }
        const float* As = smf + (ti % NSTAGE) * 2 * TILEF;
        const float* Bs = As + TILEF;
#pragma unroll
        for (int ks = 0; ks < 4; ks++) {
            int kk = ks * 8;
            uint32_t a[2][4];
#pragma unroll
            for (int mt = 0; mt < 2; mt++) {
                const float* ap = As + (wm + mt * 16) * LDW + kk;
                a[mt][0] = __float_as_uint(ap[g * LDW + c]);
                a[mt][1] = __float_as_uint(ap[(g + 8) * LDW + c]);
                a[mt][2] = __float_as_uint(ap[g * LDW + c + 4]);
                a[mt][3] = __float_as_uint(ap[(g + 8) * LDW + c + 4]);
            }
#pragma unroll
            for (int nt = 0; nt < 8; nt++) {
                const float* bp = Bs + (wn + nt * 8 + g) * LDW + kk;
                uint32_t b0 = __float_as_uint(bp[c]);
                uint32_t b1 = __float_as_uint(bp[c + 4]);
                MMA(acc[0][nt], a[0], b0, b1);
                MMA(acc[1][nt], a[1], b0, b1);
            }
        }
    }

    // epilogue: out = (acc + v*m) * m
#pragma unroll
    for (int mt = 0; mt < 2; mt++) {
#pragma unroll
        for (int nt = 0; nt < 8; nt++) {
            int cb = colBase + wn + nt * 8 + 2 * c;
#pragma unroll
            for (int half = 0; half < 2; half++) {
                int r = rowBase + wm + mt * 16 + g + half * 8;
                float m = masks[r];
                float v0 = qkv[(size_t)r * QKVW + 1024 + cb];
                float v1 = qkv[(size_t)r * QKVW + 1024 + cb + 1];
                float o0 = (acc[mt][nt][half * 2 + 0] + v0 * m) * m;
                float o1 = (acc[mt][nt][half * 2 + 1] + v1 * m) * m;
                *(float2*)(out + (size_t)r * D_ + cb) = make_float2(o0, o1);
            }
        }
    }
}

// ---------------- fused attention: scores + softmax + ctx -------------------
#define QT 32
#define SCPAD 224
#define ATT_SMEM ((QT*132 + QT*132 + QT*SCPAD)*4)
__global__ void __launch_bounds__(256)
att_kernel(const float* __restrict__ qkv, const float* __restrict__ masks,
           float* __restrict__ ctx) {
    extern __shared__ float smf[];
    float* Qs = smf;                 // [QT][132]
    float* Ks = smf + QT * 132;      // [QT][132]
    float* Sc = smf + 2 * QT * 132;  // [QT][SCPAD]
    int tid = threadIdx.x;
    int bh = blockIdx.y;
    int b = bh >> 2, h = bh & 3;
    int qbase = blockIdx.x * QT;
    int nq = T_ - qbase; if (nq > QT) nq = QT;
    const int qoff = h * DK_;
    const int koff = D_ + h * DK_;
    const int voff = 1024 + h * DK_;

    for (int f = tid; f < QT * 32; f += 256) {
        int row = f >> 5, seg = f & 31;
        float4 v = make_float4(0.f, 0.f, 0.f, 0.f);
        if (row < nq)
            v = *(const float4*)(qkv + (size_t)(b * T_ + qbase + row) * QKVW + qoff + seg * 4);
        *(float4*)(Qs + row * 132 + seg * 4) = v;
    }
    __syncthreads();

    int tx = tid & 15, ty = tid >> 4;
    const float scale = 0.08838834764831845f;
    for (int kbase = 0; kbase < T_; kbase += 32) {
        int nk2 = T_ - kbase; if (nk2 > 32) nk2 = 32;
        for (int f = tid; f < 32 * 32; f += 256) {
            int row = f >> 5, seg = f & 31;
            float4 v = make_float4(0.f, 0.f, 0.f, 0.f);
            if (row < nk2)
                v = *(const float4*)(qkv + (size_t)(b * T_ + kbase + row) * QKVW + koff + seg * 4);
            *(float4*)(Ks + row * 132 + seg * 4) = v;
        }
        __syncthreads();
        float acc[2][2] = {};
        const float* q0p = Qs + (ty * 2 + 0) * 132;
        const float* q1p = Qs + (ty * 2 + 1) * 132;
        const float* k0p = Ks + (tx * 2 + 0) * 132;
        const float* k1p = Ks + (tx * 2 + 1) * 132;
#pragma unroll 4
        for (int d = 0; d < DK_; d++) {
            float q0 = q0p[d], q1 = q1p[d];
            float k0 = k0p[d], k1 = k1p[d];
            acc[0][0] += q0 * k0; acc[0][1] += q0 * k1;
            acc[1][0] += q1 * k0; acc[1][1] += q1 * k1;
        }
#pragma unroll
        for (int i = 0; i < 2; i++) {
#pragma unroll
            for (int j = 0; j < 2; j++) {
                int kc = kbase + tx * 2 + j;
                if (kc < T_) {
                    float s = acc[i][j] * scale;
                    if (masks[b * T_ + kc] <= 0.f) s = -3.0e38f;
                    Sc[(ty * 2 + i) * SCPAD + kc] = s;
                }
            }
        }
        __syncthreads();
    }

    int lane = tid & 31, wrp = tid >> 5;
#pragma unroll
    for (int i = 0; i < 4; i++) {
        int row = wrp * 4 + i;
        float* p = Sc + row * SCPAD;
        float mx = -3.4e38f;
        for (int k = lane; k < T_; k += 32) mx = fmaxf(mx, p[k]);
#pragma unroll
        for (int o = 16; o; o >>= 1) mx = fmaxf(mx, __shfl_xor_sync(~0u, mx, o));
        float sum = 0.f;
        for (int k = lane; k < T_; k += 32) {
            float e = expf(p[k] - mx);
            p[k] = e;
            sum += e;
        }
#pragma unroll
        for (int o = 16; o; o >>= 1) sum += __shfl_xor_sync(~0u, sum, o);
        float inv = 1.f / sum;
        for (int k = lane; k < T_; k += 32) p[k] *= inv;
    }
    __syncthreads();

    int c = tid & 127;
    int rg = (tid >> 7) * 16;
    float acc[16];
#pragma unroll
    for (int i = 0; i < 16; i++) acc[i] = 0.f;
    for (int k = 0; k < T_; k++) {
        float vk = qkv[(size_t)(b * T_ + k) * QKVW + voff + c];
#pragma unroll
        for (int i = 0; i < 16; i++)
            acc[i] += Sc[(rg + i) * SCPAD + k] * vk;
    }
#pragma unroll
    for (int i = 0; i < 16; i++) {
        int r = qbase + rg + i;
        if (r < T_)
            ctx[(size_t)(b * T_ + r) * D_ + h * DK_ + c] = rna_tf32(acc[i]);
    }
}

// ---------------- launch ------------------------------------------------------
extern "C" void kernel_launch(void* const* d_in, const int* in_sizes, int n_in,
                              void* d_out, int out_size) {
    const float* x     = (const float*)d_in[0];
    const float* masks = (const float*)d_in[1];
    const float* ln0_w = (const float*)d_in[2];
    const float* ln0_b = (const float*)d_in[3];
    const float* ln1_w = (const float*)d_in[4];
    const float* ln1_b = (const float*)d_in[5];
    const float* qkv_w = (const float*)d_in[6];
    const float* qkv_b = (const float*)d_in[7];
    const float* out_w = (const float*)d_in[8];
    const float* out_b = (const float*)d_in[9];
    const float* fsmn_w= (const float*)d_in[10];
    const float* w1    = (const float*)d_in[11];
    const float* b1    = (const float*)d_in[12];
    const float* w2    = (const float*)d_in[13];
    const float* b2    = (const float*)d_in[14];
    float* out = (float*)d_out;

    float *h, *qkv, *vm, *fsmn, *ctx, *x1, *mid;
    float *qkv_wt, *out_wt, *w1t, *w2t;
    cudaGetSymbolAddress((void**)&h,      g_h);
    cudaGetSymbolAddress((void**)&qkv,    g_qkv);
    cudaGetSymbolAddress((void**)&vm,     g_vm);
    cudaGetSymbolAddress((void**)&fsmn,   g_fsmn);
    cudaGetSymbolAddress((void**)&ctx,    g_ctx);
    cudaGetSymbolAddress((void**)&x1,     g_x1);
    cudaGetSymbolAddress((void**)&mid,    g_mid);
    cudaGetSymbolAddress((void**)&qkv_wt, g_qkv_wt);
    cudaGetSymbolAddress((void**)&out_wt, g_out_wt);
    cudaGetSymbolAddress((void**)&w1t,    g_w1t);
    cudaGetSymbolAddress((void**)&w2t,    g_w2t);

    cudaFuncSetAttribute(tgemm, cudaFuncAttributeMaxDynamicSharedMemorySize, DSMEM_BYTES);
    cudaFuncSetAttribute(tconv, cudaFuncAttributeMaxDynamicSharedMemorySize, DSMEM_BYTES);
    cudaFuncSetAttribute(att_kernel, cudaFuncAttributeMaxDynamicSharedMemorySize, ATT_SMEM);

    // weight prep (tf32-rounded, [N,K] layouts)
    transpose_rna<<<dim3(QKVW / 32, D_ / 32), dim3(32, 8)>>>(qkv_w, qkv_wt, D_, QKVW);
    transpose_rna<<<dim3(D_ / 32, D_ / 32), dim3(32, 8)>>>(out_w, out_wt, D_, D_);
    transpose_rna<<<dim3(2048 / 32, D_ / 32), dim3(32, 8)>>>(w1, w1t, D_, 2048);
    transpose_rna<<<dim3(D_ / 32, 2048 / 32), dim3(32, 8)>>>(w2, w2t, 2048, D_);
    kw_transpose<<<(11 * D_ * D_ + 255) / 256, 256>>>(fsmn_w);

    // LN0 (rounded)
    ln_kernel<<<R_, 128>>>(x, ln0_w, ln0_b, h);

    // QKV (epi 5: also writes vm for v columns)
    tgemm<<<dim3(QKVW / 128, R_ / 128), 256, DSMEM_BYTES>>>(h, qkv_wt, qkv_b, qkv,
                                                            QKVW, D_, 5, masks, vm);

    // FSMN conv
    tconv<<<dim3(D_ / 128, R_ / 128), 256, DSMEM_BYTES>>>(vm, qkv, masks, fsmn);

    // fused attention
    att_kernel<<<dim3((T_ + QT - 1) / QT, B_ * H_), 256, ATT_SMEM>>>(qkv, masks, ctx);

    // out proj + fsmn + residual
    tgemm<<<dim3(D_ / 128, R_ / 128), 256, DSMEM_BYTES>>>(ctx, out_wt, out_b, x1,
                                                          D_, D_, 2, fsmn, (float*)x);
    // LN1
    ln_kernel<<<R_, 128>>>(x1, ln1_w, ln1_b, h);

    // FFN
    tgemm<<<dim3(2048 / 128, R_ / 128), 256, DSMEM_BYTES>>>(h, w1t, b1, mid,
                                                            2048, D_, 1, nullptr, nullptr);
    tgemm<<<dim3(D_ / 128, R_ / 128), 256, DSMEM_BYTES>>>(mid, w2t, b2, out,
                                                          D_, 2048, 3, x1, nullptr);
    (void)in_sizes; (void)n_in; (void)out_size;
}